// round 11
// baseline (speedup 1.0000x reference)
#include <cuda_runtime.h>
#include <cooperative_groups.h>

namespace cg = cooperative_groups;

#define B 64
#define N 16384
#define M 64
#define FULLM 0xFFFFFFFFu

#define NCHUNKS 4
#define BCHUNK  (B / NCHUNKS)   // 16 batches per chunk

// scratch (device globals — no allocation allowed)
__device__ float g_s[B * N];       // exp(beta*cos) from k1
__device__ float g_part[B * 64];   // per-block partial sums of exp

// ---------------------------------------------------------------------------
// k1: exp(beta*cos) per row + deterministic per-block partial sum.
// 4 lanes/row, 4 rows/thread -> 16 LDG.128.CS in flight.
// Grid = (64, BCHUNK); batch = blockIdx.y + b0.
// ---------------------------------------------------------------------------
__global__ __launch_bounds__(256) void k1_logits(
    const float* __restrict__ key,    // [B, M]
    const float* __restrict__ beta,   // [B, 1]
    const float* __restrict__ mem,    // [B, N, M]
    const float* __restrict__ last,   // [B, N] (L2 prefetch only)
    int b0)
{
    const int b    = blockIdx.y + b0;
    const int tid  = threadIdx.x;
    const int l    = tid & 3;
    const int grp  = tid >> 2;
    const int row0 = blockIdx.x * 256;

    // L2 prefetch of last[] (this block's 1KB slice)
    if (tid < 8) {
        const float* lpre = last + (size_t)b * N + blockIdx.x * 256 + tid * 32;
        asm volatile("prefetch.global.L2 [%0];" :: "l"(lpre));
    }

    const float4* kp = reinterpret_cast<const float4*>(key + b * M);
    float4 k4[4];
#pragma unroll
    for (int j = 0; j < 4; ++j) k4[j] = kp[l + 4 * j];

    float ks = 0.0f;
#pragma unroll
    for (int j = 0; j < 4; ++j)
        ks += k4[j].x * k4[j].x + k4[j].y * k4[j].y
            + k4[j].z * k4[j].z + k4[j].w * k4[j].w;

    float4 m4[4][4];
#pragma unroll
    for (int u = 0; u < 4; ++u) {
        const int row = row0 + u * 64 + grp;
        const float4* mp = reinterpret_cast<const float4*>(
            mem + ((size_t)b * N + row) * M);
#pragma unroll
        for (int j = 0; j < 4; ++j) m4[u][j] = __ldcs(mp + l + 4 * j);
    }

    float dt[4] = {0.f, 0.f, 0.f, 0.f}, ms[4] = {0.f, 0.f, 0.f, 0.f};
#pragma unroll
    for (int u = 0; u < 4; ++u)
#pragma unroll
        for (int j = 0; j < 4; ++j) {
            dt[u] += k4[j].x * m4[u][j].x + k4[j].y * m4[u][j].y
                   + k4[j].z * m4[u][j].z + k4[j].w * m4[u][j].w;
            ms[u] += m4[u][j].x * m4[u][j].x + m4[u][j].y * m4[u][j].y
                   + m4[u][j].z * m4[u][j].z + m4[u][j].w * m4[u][j].w;
        }

#pragma unroll
    for (int off = 1; off <= 2; off <<= 1) {
        ks += __shfl_xor_sync(FULLM, ks, off);
#pragma unroll
        for (int u = 0; u < 4; ++u) {
            dt[u] += __shfl_xor_sync(FULLM, dt[u], off);
            ms[u] += __shfl_xor_sync(FULLM, ms[u], off);
        }
    }

    float esum = 0.0f;
    if (l == 0) {
        const float kn = sqrtf(ks);
        const float be = __ldg(beta + b);
#pragma unroll
        for (int u = 0; u < 4; ++u) {
            const int row = row0 + u * 64 + grp;
            const float denom = fmaxf(kn * sqrtf(ms[u]), 1e-8f);
            const float e = __expf(be * (dt[u] / denom));
            g_s[b * N + row] = e;
            esum += e;
        }
    }

    __shared__ float sred[8];
#pragma unroll
    for (int o = 16; o > 0; o >>= 1)
        esum += __shfl_xor_sync(FULLM, esum, o);
    if ((tid & 31) == 0) sred[tid >> 5] = esum;
    __syncthreads();
    if (tid == 0) {
        float s = 0.0f;
#pragma unroll
        for (int w = 0; w < 8; ++w) s += sred[w];
        g_part[b * 64 + blockIdx.x] = s;
    }
}

// ---------------------------------------------------------------------------
// k2: cluster-4 epilogue chunk. Grid = (BCHUNK*4) CTAs x 512 thr; CTA q of
// batch b owns elems [q*4096, (q+1)*4096). 4 LDG.128 + 2 STG.128 per thread;
// halos via shuffles + smem warp edges; renorm sum across the 4-CTA cluster
// via DSMEM in fixed rank order (deterministic).
// ---------------------------------------------------------------------------
__global__ __launch_bounds__(512) __cluster_dims__(4, 1, 1)
void k2_address(
    const float* __restrict__ gate,     // [B,1]
    const float* __restrict__ shift,    // [B,3]
    const float* __restrict__ sharpen,  // [B,1]
    const float* __restrict__ last,     // [B,N]
    float* __restrict__ out,            // [B,N]
    int b0)
{
    cg::cluster_group cluster = cg::this_cluster();

    const int b    = (blockIdx.x >> 2) + b0;
    const int q    = blockIdx.x & 3;     // quarter of the batch (cluster rank)
    const int tid  = threadIdx.x;
    const int warp = tid >> 5;           // 0..15
    const int lane = tid & 31;

    __shared__ float sred[16];
    __shared__ float sS;
    __shared__ float edgeL[16];
    __shared__ float edgeR[16];
    __shared__ float sCtaL, sCtaR;
    __shared__ float cpsum;              // DSMEM target

    // ---- softmax denominator from k1 partials (warp 0, overlapped) ----
    if (warp == 0) {
        float S = g_part[b * 64 + lane] + g_part[b * 64 + 32 + lane];
#pragma unroll
        for (int o = 16; o > 0; o >>= 1)
            S += __shfl_xor_sync(FULLM, S, o);
        if (lane == 0) sS = S;
    }

    // ---- vector loads: 2 float4 of exp + 2 of last (coalesced, L2-hot) ----
    const int base4 = (b << 12) + (q << 10) + (warp << 6);  // float4 units
    const float4* sp4 = reinterpret_cast<const float4*>(g_s);
    const float4* lp4 = reinterpret_cast<const float4*>(last);
    float4 e4[2], a4[2];
#pragma unroll
    for (int k = 0; k < 2; ++k) {
        e4[k] = sp4[base4 + k * 32 + lane];
        a4[k] = lp4[base4 + k * 32 + lane];
    }
    __syncthreads();  // sS ready

    const float g  = __ldg(gate + b);
    const float gS = g / sS;
    const float og = 1.0f - g;
    const float s0 = __ldg(shift + b * 3 + 0);
    const float s1 = __ldg(shift + b * 3 + 1);
    const float s2 = __ldg(shift + b * 3 + 2);
    const float sh = __ldg(sharpen + b);

    // ---- gate interpolation in registers ----
    float4 w4[2];
#pragma unroll
    for (int k = 0; k < 2; ++k) {
        w4[k].x = fmaf(gS, e4[k].x, og * a4[k].x);
        w4[k].y = fmaf(gS, e4[k].y, og * a4[k].y);
        w4[k].z = fmaf(gS, e4[k].z, og * a4[k].z);
        w4[k].w = fmaf(gS, e4[k].w, og * a4[k].w);
    }

    // warp edges to smem; CTA edges (circular) by 2 threads (L2-hit loads)
    if (lane == 0)  edgeL[warp] = w4[0].x;
    if (lane == 31) edgeR[warp] = w4[1].w;
    if (tid == 0) {
        const int i = b * N + (((q << 12) + N - 1) & (N - 1));
        sCtaL = fmaf(gS, g_s[i], og * last[i]);
    }
    if (tid == 511) {
        const int i = b * N + (((q << 12) + 4096) & (N - 1));
        sCtaR = fmaf(gS, g_s[i], og * last[i]);
    }
    __syncthreads();

    const float wrapL = (warp == 0)  ? sCtaL : edgeR[warp - 1];
    const float wrapR = (warp == 15) ? sCtaR : edgeL[warp + 1];

    // ---- circular 3-tap conv + sharpen, halos via shuffles ----
    const float prevw = __shfl_sync(FULLM, w4[0].w, 31);  // lane31's k=0 .w
    const float nextx = __shfl_sync(FULLM, w4[1].x, 0);   // lane0's  k=1 .x

    float psum = 0.0f;
    float4 p4[2];
#pragma unroll
    for (int k = 0; k < 2; ++k) {
        float left = __shfl_up_sync(FULLM, w4[k].w, 1);
        if (lane == 0) left = (k == 0) ? wrapL : prevw;
        float right = __shfl_down_sync(FULLM, w4[k].x, 1);
        if (lane == 31) right = (k == 1) ? wrapR : nextx;

        p4[k].x = __powf(s0 * left    + s1 * w4[k].x + s2 * w4[k].y, sh);
        p4[k].y = __powf(s0 * w4[k].x + s1 * w4[k].y + s2 * w4[k].z, sh);
        p4[k].z = __powf(s0 * w4[k].y + s1 * w4[k].z + s2 * w4[k].w, sh);
        p4[k].w = __powf(s0 * w4[k].z + s1 * w4[k].w + s2 * right,  sh);
        psum += p4[k].x + p4[k].y + p4[k].z + p4[k].w;
    }

    // ---- CTA psum reduce (deterministic) ----
#pragma unroll
    for (int o = 16; o > 0; o >>= 1)
        psum += __shfl_xor_sync(FULLM, psum, o);
    if (lane == 0) sred[warp] = psum;
    __syncthreads();
    if (warp == 0) {
        float x = (lane < 16) ? sred[lane] : 0.0f;
#pragma unroll
        for (int o = 8; o > 0; o >>= 1)
            x += __shfl_xor_sync(FULLM, x, o);
        if (lane == 0) cpsum = x;
    }

    // ---- cluster combine via DSMEM (fixed rank order -> deterministic) ----
    cluster.sync();
    float P = 0.0f;
#pragma unroll
    for (int r = 0; r < 4; ++r)
        P += *cluster.map_shared_rank(&cpsum, r);
    cluster.sync();  // keep peer smem alive until all CTAs have read

    const float invP = 1.0f / (P + 1e-16f);

    float4* op4 = reinterpret_cast<float4*>(out);
#pragma unroll
    for (int k = 0; k < 2; ++k) {
        float4 p = p4[k];
        p.x *= invP; p.y *= invP; p.z *= invP; p.w *= invP;
        op4[base4 + k * 32 + lane] = p;
    }
}

extern "C" void kernel_launch(void* const* d_in, const int* in_sizes, int n_in,
                              void* d_out, int out_size) {
    const float* key     = (const float*)d_in[0];
    const float* beta    = (const float*)d_in[1];
    const float* gate    = (const float*)d_in[2];
    const float* shift   = (const float*)d_in[3];
    const float* sharpen = (const float*)d_in[4];
    const float* last    = (const float*)d_in[5];
    const float* mem     = (const float*)d_in[6];
    float* out = (float*)d_out;

    // one-time resource creation (no device memory involved)
    static cudaStream_t s2 = nullptr;
    static cudaEvent_t  ev[NCHUNKS], evDone;
    if (!s2) {
        cudaStreamCreateWithFlags(&s2, cudaStreamNonBlocking);
        for (int i = 0; i < NCHUNKS; ++i)
            cudaEventCreateWithFlags(&ev[i], cudaEventDisableTiming);
        cudaEventCreateWithFlags(&evDone, cudaEventDisableTiming);
    }

    // pipelined: k1 chunk c on main stream; k2 chunk c on s2 after ev[c].
    for (int c = 0; c < NCHUNKS; ++c) {
        dim3 g1(N / 256, BCHUNK);
        k1_logits<<<g1, 256>>>(key, beta, mem, last, c * BCHUNK);
        cudaEventRecord(ev[c], 0);
        cudaStreamWaitEvent(s2, ev[c], 0);
        k2_address<<<BCHUNK * 4, 512, 0, s2>>>(gate, shift, sharpen, last, out,
                                               c * BCHUNK);
    }
    // rejoin forked stream into the captured stream
    cudaEventRecord(evDone, s2);
    cudaStreamWaitEvent(0, evDone, 0);
}

// round 12
// speedup vs baseline: 1.3158x; 1.3158x over previous
#include <cuda_runtime.h>
#include <cooperative_groups.h>

namespace cg = cooperative_groups;

#define B 64
#define N 16384
#define M 64
#define FULLM 0xFFFFFFFFu

// scratch (device globals — no allocation allowed)
__device__ float g_s[B * N];        // exp(beta*cos) from k1
__device__ float g_part[B * 256];   // per-block partial sums (k1 grid.x = 256)

// ---------------------------------------------------------------------------
// k1: exp(beta*cos) per row + deterministic per-block partial sum.
// 8 lanes/row (lane: 2 float4 = 32B of the 256B row), 2 rows/thread ->
// 4 LDG.128.CS in flight; ~55 regs -> 4-5 blocks/SM (2x warps vs old tiling).
// Block = 256 thr -> 64 rows. Grid = (N/64, B) = (256, B).
// ---------------------------------------------------------------------------
__global__ __launch_bounds__(256) void k1_logits(
    const float* __restrict__ key,    // [B, M]
    const float* __restrict__ beta,   // [B, 1]
    const float* __restrict__ mem)    // [B, N, M]
{
    const int b    = blockIdx.y;
    const int tid  = threadIdx.x;
    const int l    = tid & 7;    // lane within 8-lane row group
    const int grp  = tid >> 3;   // 0..31
    const int row0 = blockIdx.x * 64;

    const float4* kp = reinterpret_cast<const float4*>(key + b * M);
    const float4 ka = kp[l];
    const float4 kb = kp[l + 8];
    float ks = ka.x * ka.x + ka.y * ka.y + ka.z * ka.z + ka.w * ka.w
             + kb.x * kb.x + kb.y * kb.y + kb.z * kb.z + kb.w * kb.w;

    // front-batched streaming loads: 4 LDG.128.CS in flight
    float4 ma[2], mb[2];
#pragma unroll
    for (int u = 0; u < 2; ++u) {
        const int row = row0 + u * 32 + grp;
        const float4* mp = reinterpret_cast<const float4*>(
            mem + ((size_t)b * N + row) * M);
        ma[u] = __ldcs(mp + l);
        mb[u] = __ldcs(mp + l + 8);
    }

    float dt[2], ms[2];
#pragma unroll
    for (int u = 0; u < 2; ++u) {
        dt[u] = ka.x * ma[u].x + ka.y * ma[u].y + ka.z * ma[u].z + ka.w * ma[u].w
              + kb.x * mb[u].x + kb.y * mb[u].y + kb.z * mb[u].z + kb.w * mb[u].w;
        ms[u] = ma[u].x * ma[u].x + ma[u].y * ma[u].y + ma[u].z * ma[u].z + ma[u].w * ma[u].w
              + mb[u].x * mb[u].x + mb[u].y * mb[u].y + mb[u].z * mb[u].z + mb[u].w * mb[u].w;
    }

    // width-8 xor reductions (lane bits 0..2 stay in the 8-group)
#pragma unroll
    for (int off = 1; off <= 4; off <<= 1) {
        ks    += __shfl_xor_sync(FULLM, ks,    off);
        dt[0] += __shfl_xor_sync(FULLM, dt[0], off);
        dt[1] += __shfl_xor_sync(FULLM, dt[1], off);
        ms[0] += __shfl_xor_sync(FULLM, ms[0], off);
        ms[1] += __shfl_xor_sync(FULLM, ms[1], off);
    }

    float esum = 0.0f;
    if (l == 0) {
        const float kn = sqrtf(ks);
        const float be = __ldg(beta + b);
#pragma unroll
        for (int u = 0; u < 2; ++u) {
            const int row = row0 + u * 32 + grp;
            const float denom = fmaxf(kn * sqrtf(ms[u]), 1e-8f);
            const float e = __expf(be * (dt[u] / denom));
            g_s[b * N + row] = e;
            esum += e;
        }
    }

    // deterministic per-block partial sum
    __shared__ float sred[8];
#pragma unroll
    for (int o = 16; o > 0; o >>= 1)
        esum += __shfl_xor_sync(FULLM, esum, o);
    if ((tid & 31) == 0) sred[tid >> 5] = esum;
    __syncthreads();
    if (tid == 0) {
        float s = 0.0f;
#pragma unroll
        for (int w = 0; w < 8; ++w) s += sred[w];
        g_part[b * 256 + blockIdx.x] = s;
    }
}

// ---------------------------------------------------------------------------
// k2 (the proven 52.4us version, only the partial-sum width changed):
// cluster-4 epilogue, 256 CTAs x 256 thr. CTA q of batch b owns elems
// [q*4096, (q+1)*4096), 4 float4/thread. Softmax denom from k1 partials
// (now 256 of them); gate + circular 3-tap (elementwise recompute) + pow;
// renorm sum combined across the 4-CTA cluster via DSMEM in fixed rank order.
// ---------------------------------------------------------------------------
__global__ __launch_bounds__(256) __cluster_dims__(4, 1, 1)
void k2_address(
    const float* __restrict__ gate,     // [B,1]
    const float* __restrict__ shift,    // [B,3]
    const float* __restrict__ sharpen,  // [B,1]
    const float* __restrict__ last,     // [B,N]
    float* __restrict__ out)            // [B,N]
{
    cg::cluster_group cluster = cg::this_cluster();

    const int cta = blockIdx.x;      // 0..255
    const int b   = cta >> 2;
    const int q   = cta & 3;         // quarter of the batch (== cluster rank)
    const int tid = threadIdx.x;
    const int lane = tid & 31;

    __shared__ float sred[8];
    __shared__ float sS;
    __shared__ float cpsum;          // this CTA's renorm partial (DSMEM target)

    // ---- softmax denominator from k1 partials (warp 0) ----
    if (tid < 32) {
        const float* pp = g_part + b * 256;
        float S = 0.0f;
#pragma unroll
        for (int j = 0; j < 8; ++j) S += pp[j * 32 + tid];
#pragma unroll
        for (int o = 16; o > 0; o >>= 1)
            S += __shfl_xor_sync(FULLM, S, o);
        if (tid == 0) sS = S;
    }

    // ---- front-batched loads: 4 float4 of exp + 4 of last ----
    const int base4 = (b << 12) + (q << 10);   // float4 index of this CTA's span
    const float4* sp4 = reinterpret_cast<const float4*>(g_s);
    const float4* lp4 = reinterpret_cast<const float4*>(last);
    float4 e4[4], a4[4];
#pragma unroll
    for (int k = 0; k < 4; ++k) {
        e4[k] = sp4[base4 + k * 256 + tid];
        a4[k] = lp4[base4 + k * 256 + tid];
    }
    __syncthreads();

    const float g  = __ldg(gate + b);
    const float gS = g / sS;
    const float og = 1.0f - g;
    const float s0 = __ldg(shift + b * 3 + 0);
    const float s1 = __ldg(shift + b * 3 + 1);
    const float s2 = __ldg(shift + b * 3 + 2);
    const float sh = __ldg(sharpen + b);

    const float* sp = g_s  + b * N;
    const float* lp = last + (size_t)b * N;

    float4 p4[4];
    float psum = 0.0f;
#pragma unroll
    for (int k = 0; k < 4; ++k) {
        const int li4  = (q << 10) + k * 256 + tid;  // batch-local float4 idx
        const int eoff = li4 * 4;
        const int lidx = (eoff + N - 1) & (N - 1);
        const int ridx = (eoff + 4) & (N - 1);
        const float wl = fmaf(gS, sp[lidx], og * lp[lidx]);
        const float wr = fmaf(gS, sp[ridx], og * lp[ridx]);

        float4 w;
        w.x = fmaf(gS, e4[k].x, og * a4[k].x);
        w.y = fmaf(gS, e4[k].y, og * a4[k].y);
        w.z = fmaf(gS, e4[k].z, og * a4[k].z);
        w.w = fmaf(gS, e4[k].w, og * a4[k].w);

        float4 p;
        p.x = __powf(s0 * wl  + s1 * w.x + s2 * w.y, sh);
        p.y = __powf(s0 * w.x + s1 * w.y + s2 * w.z, sh);
        p.z = __powf(s0 * w.y + s1 * w.z + s2 * w.w, sh);
        p.w = __powf(s0 * w.z + s1 * w.w + s2 * wr,  sh);
        p4[k] = p;
        psum += p.x + p.y + p.z + p.w;
    }

    // ---- CTA-level psum reduce (deterministic) ----
#pragma unroll
    for (int o = 16; o > 0; o >>= 1)
        psum += __shfl_xor_sync(FULLM, psum, o);
    if (lane == 0) sred[tid >> 5] = psum;
    __syncthreads();
    if (tid == 0) {
        float x = 0.0f;
#pragma unroll
        for (int w = 0; w < 8; ++w) x += sred[w];
        cpsum = x;
    }

    // ---- cluster-level combine via DSMEM (fixed rank order) ----
    cluster.sync();
    float P = 0.0f;
#pragma unroll
    for (int r = 0; r < 4; ++r) {
        const float* peer = cluster.map_shared_rank(&cpsum, r);
        P += *peer;
    }
    cluster.sync();  // keep peers' smem alive until everyone has read

    const float invP = 1.0f / (P + 1e-16f);

    float4* op4 = reinterpret_cast<float4*>(out);
#pragma unroll
    for (int k = 0; k < 4; ++k) {
        float4 p = p4[k];
        p.x *= invP; p.y *= invP; p.z *= invP; p.w *= invP;
        op4[base4 + k * 256 + tid] = p;
    }
}

extern "C" void kernel_launch(void* const* d_in, const int* in_sizes, int n_in,
                              void* d_out, int out_size) {
    const float* key     = (const float*)d_in[0];
    const float* beta    = (const float*)d_in[1];
    const float* gate    = (const float*)d_in[2];
    const float* shift   = (const float*)d_in[3];
    const float* sharpen = (const float*)d_in[4];
    const float* last    = (const float*)d_in[5];
    const float* mem     = (const float*)d_in[6];
    float* out = (float*)d_out;

    dim3 g1(N / 64, B);
    k1_logits<<<g1, 256>>>(key, beta, mem);
    k2_address<<<B * 4, 256>>>(gate, shift, sharpen, last, out);
}

// round 13
// speedup vs baseline: 1.3329x; 1.0130x over previous
#include <cuda_runtime.h>
#include <cooperative_groups.h>

namespace cg = cooperative_groups;

#define B 64
#define N 16384
#define M 64
#define FULLM 0xFFFFFFFFu

// scratch (device globals — no allocation allowed)
__device__ float g_s[B * N];        // exp(beta*cos) from k1
__device__ float g_part[B * 256];   // per-block partial sums (k1 grid.x = 256)

// ---------------------------------------------------------------------------
// k1 (proven 41.7us): exp(beta*cos) per row + deterministic per-block partial
// sum. 8 lanes/row, 2 rows/thread -> 4 LDG.128.CS in flight; ~55 regs.
// Block = 256 thr -> 64 rows. Grid = (256, B).
// ---------------------------------------------------------------------------
__global__ __launch_bounds__(256) void k1_logits(
    const float* __restrict__ key,    // [B, M]
    const float* __restrict__ beta,   // [B, 1]
    const float* __restrict__ mem)    // [B, N, M]
{
    const int b    = blockIdx.y;
    const int tid  = threadIdx.x;
    const int l    = tid & 7;    // lane within 8-lane row group
    const int grp  = tid >> 3;   // 0..31
    const int row0 = blockIdx.x * 64;

    const float4* kp = reinterpret_cast<const float4*>(key + b * M);
    const float4 ka = kp[l];
    const float4 kb = kp[l + 8];
    float ks = ka.x * ka.x + ka.y * ka.y + ka.z * ka.z + ka.w * ka.w
             + kb.x * kb.x + kb.y * kb.y + kb.z * kb.z + kb.w * kb.w;

    float4 ma[2], mb[2];
#pragma unroll
    for (int u = 0; u < 2; ++u) {
        const int row = row0 + u * 32 + grp;
        const float4* mp = reinterpret_cast<const float4*>(
            mem + ((size_t)b * N + row) * M);
        ma[u] = __ldcs(mp + l);
        mb[u] = __ldcs(mp + l + 8);
    }

    float dt[2], ms[2];
#pragma unroll
    for (int u = 0; u < 2; ++u) {
        dt[u] = ka.x * ma[u].x + ka.y * ma[u].y + ka.z * ma[u].z + ka.w * ma[u].w
              + kb.x * mb[u].x + kb.y * mb[u].y + kb.z * mb[u].z + kb.w * mb[u].w;
        ms[u] = ma[u].x * ma[u].x + ma[u].y * ma[u].y + ma[u].z * ma[u].z + ma[u].w * ma[u].w
              + mb[u].x * mb[u].x + mb[u].y * mb[u].y + mb[u].z * mb[u].z + mb[u].w * mb[u].w;
    }

#pragma unroll
    for (int off = 1; off <= 4; off <<= 1) {
        ks    += __shfl_xor_sync(FULLM, ks,    off);
        dt[0] += __shfl_xor_sync(FULLM, dt[0], off);
        dt[1] += __shfl_xor_sync(FULLM, dt[1], off);
        ms[0] += __shfl_xor_sync(FULLM, ms[0], off);
        ms[1] += __shfl_xor_sync(FULLM, ms[1], off);
    }

    float esum = 0.0f;
    if (l == 0) {
        const float kn = sqrtf(ks);
        const float be = __ldg(beta + b);
#pragma unroll
        for (int u = 0; u < 2; ++u) {
            const int row = row0 + u * 32 + grp;
            const float denom = fmaxf(kn * sqrtf(ms[u]), 1e-8f);
            const float e = __expf(be * (dt[u] / denom));
            g_s[b * N + row] = e;
            esum += e;
        }
    }

    __shared__ float sred[8];
#pragma unroll
    for (int o = 16; o > 0; o >>= 1)
        esum += __shfl_xor_sync(FULLM, esum, o);
    if ((tid & 31) == 0) sred[tid >> 5] = esum;
    __syncthreads();
    if (tid == 0) {
        float s = 0.0f;
#pragma unroll
        for (int w = 0; w < 8; ++w) s += sred[w];
        g_part[b * 256 + blockIdx.x] = s;
    }
}

// ---------------------------------------------------------------------------
// k2 with PDL: launched with programmatic stream serialization, so it starts
// WHILE k1 runs. Preamble loads everything independent of k1 (last + scalars),
// then cudaGridDependencySynchronize() waits for k1 completion (full memory
// visibility: k1 uses the implicit end-of-grid trigger), then reads the
// L2-hot g_s / g_part and finishes. Cluster-4, 256 CTAs x 256 thr; renorm
// sum combined across the cluster via DSMEM in fixed rank order.
// ---------------------------------------------------------------------------
__global__ __launch_bounds__(256) __cluster_dims__(4, 1, 1)
void k2_address(
    const float* __restrict__ gate,     // [B,1]
    const float* __restrict__ shift,    // [B,3]
    const float* __restrict__ sharpen,  // [B,1]
    const float* __restrict__ last,     // [B,N]
    float* __restrict__ out)            // [B,N]
{
    cg::cluster_group cluster = cg::this_cluster();

    const int cta = blockIdx.x;      // 0..255
    const int b   = cta >> 2;
    const int q   = cta & 3;         // quarter of the batch (== cluster rank)
    const int tid = threadIdx.x;
    const int lane = tid & 31;

    __shared__ float sred[8];
    __shared__ float sS;
    __shared__ float cpsum;          // this CTA's renorm partial (DSMEM target)

    // ======= PDL preamble: everything independent of k1's output =======
    const int base4 = (b << 12) + (q << 10);   // float4 index of this CTA's span
    const float4* lp4 = reinterpret_cast<const float4*>(last);
    const float*  lp  = last + (size_t)b * N;

    float4 a4[4];
    float  ll[4], lr[4];             // last[] at halo positions
    int    lidx[4], ridx[4];
#pragma unroll
    for (int k = 0; k < 4; ++k) {
        a4[k] = lp4[base4 + k * 256 + tid];
        const int eoff = ((q << 10) + k * 256 + tid) * 4;
        lidx[k] = (eoff + N - 1) & (N - 1);
        ridx[k] = (eoff + 4) & (N - 1);
        ll[k] = lp[lidx[k]];
        lr[k] = lp[ridx[k]];
    }
    const float g  = __ldg(gate + b);
    const float og = 1.0f - g;
    const float s0 = __ldg(shift + b * 3 + 0);
    const float s1 = __ldg(shift + b * 3 + 1);
    const float s2 = __ldg(shift + b * 3 + 2);
    const float sh = __ldg(sharpen + b);

    // ======= wait for k1 grid completion (memory-visible) =======
    cudaGridDependencySynchronize();

    // ---- softmax denominator from k1 partials (warp 0) ----
    if (tid < 32) {
        const float* pp = g_part + b * 256;
        float S = 0.0f;
#pragma unroll
        for (int j = 0; j < 8; ++j) S += pp[j * 32 + tid];
#pragma unroll
        for (int o = 16; o > 0; o >>= 1)
            S += __shfl_xor_sync(FULLM, S, o);
        if (tid == 0) sS = S;
    }

    // ---- loads of k1 output (L2-hot) ----
    const float4* sp4 = reinterpret_cast<const float4*>(g_s);
    const float*  sp  = g_s + b * N;
    float4 e4[4];
    float  sl[4], sr[4];
#pragma unroll
    for (int k = 0; k < 4; ++k) {
        e4[k] = sp4[base4 + k * 256 + tid];
        sl[k] = sp[lidx[k]];
        sr[k] = sp[ridx[k]];
    }
    __syncthreads();  // sS ready

    const float gS = g / sS;

    float4 p4[4];
    float psum = 0.0f;
#pragma unroll
    for (int k = 0; k < 4; ++k) {
        const float wl = fmaf(gS, sl[k], og * ll[k]);
        const float wr = fmaf(gS, sr[k], og * lr[k]);

        float4 w;
        w.x = fmaf(gS, e4[k].x, og * a4[k].x);
        w.y = fmaf(gS, e4[k].y, og * a4[k].y);
        w.z = fmaf(gS, e4[k].z, og * a4[k].z);
        w.w = fmaf(gS, e4[k].w, og * a4[k].w);

        float4 p;
        p.x = __powf(s0 * wl  + s1 * w.x + s2 * w.y, sh);
        p.y = __powf(s0 * w.x + s1 * w.y + s2 * w.z, sh);
        p.z = __powf(s0 * w.y + s1 * w.z + s2 * w.w, sh);
        p.w = __powf(s0 * w.z + s1 * w.w + s2 * wr,  sh);
        p4[k] = p;
        psum += p.x + p.y + p.z + p.w;
    }

    // ---- CTA-level psum reduce (deterministic) ----
#pragma unroll
    for (int o = 16; o > 0; o >>= 1)
        psum += __shfl_xor_sync(FULLM, psum, o);
    if (lane == 0) sred[tid >> 5] = psum;
    __syncthreads();
    if (tid == 0) {
        float x = 0.0f;
#pragma unroll
        for (int w = 0; w < 8; ++w) x += sred[w];
        cpsum = x;
    }

    // ---- cluster-level combine via DSMEM (fixed rank order) ----
    cluster.sync();
    float P = 0.0f;
#pragma unroll
    for (int r = 0; r < 4; ++r) {
        const float* peer = cluster.map_shared_rank(&cpsum, r);
        P += *peer;
    }
    cluster.sync();  // keep peers' smem alive until everyone has read

    const float invP = 1.0f / (P + 1e-16f);

    float4* op4 = reinterpret_cast<float4*>(out);
#pragma unroll
    for (int k = 0; k < 4; ++k) {
        float4 p = p4[k];
        p.x *= invP; p.y *= invP; p.z *= invP; p.w *= invP;
        op4[base4 + k * 256 + tid] = p;
    }
}

extern "C" void kernel_launch(void* const* d_in, const int* in_sizes, int n_in,
                              void* d_out, int out_size) {
    const float* key     = (const float*)d_in[0];
    const float* beta    = (const float*)d_in[1];
    const float* gate    = (const float*)d_in[2];
    const float* shift   = (const float*)d_in[3];
    const float* sharpen = (const float*)d_in[4];
    const float* last    = (const float*)d_in[5];
    const float* mem     = (const float*)d_in[6];
    float* out = (float*)d_out;

    dim3 g1(N / 64, B);
    k1_logits<<<g1, 256>>>(key, beta, mem);

    // k2 with programmatic dependent launch: overlap its preamble with k1.
    cudaLaunchConfig_t cfg = {};
    cfg.gridDim  = dim3(B * 4);
    cfg.blockDim = dim3(256);
    cudaLaunchAttribute attrs[1];
    attrs[0].id = cudaLaunchAttributeProgrammaticStreamSerialization;
    attrs[0].val.programmaticStreamSerializationAllowed = 1;
    cfg.attrs = attrs;
    cfg.numAttrs = 1;
    cudaLaunchKernelEx(&cfg, k2_address, gate, shift, sharpen, last, out);
}

// round 14
// speedup vs baseline: 1.3603x; 1.0206x over previous
#include <cuda_runtime.h>
#include <cooperative_groups.h>

namespace cg = cooperative_groups;

#define B 64
#define N 16384
#define M 64
#define FULLM 0xFFFFFFFFu

// scratch (device globals — no allocation allowed)
__device__ float g_s[B * N];        // exp(beta*cos) from k1
__device__ float g_part[B * 256];   // per-block partial sums (k1 grid.x = 256)

// ---------------------------------------------------------------------------
// k1 (proven ~41.7us): exp(beta*cos) per row + deterministic per-block
// partial sum. 8 lanes/row, 2 rows/thread -> 4 LDG.128.CS in flight; ~55 regs.
// Block = 256 thr -> 64 rows. Grid = (256, B).
// ---------------------------------------------------------------------------
__global__ __launch_bounds__(256) void k1_logits(
    const float* __restrict__ key,    // [B, M]
    const float* __restrict__ beta,   // [B, 1]
    const float* __restrict__ mem)    // [B, N, M]
{
    const int b    = blockIdx.y;
    const int tid  = threadIdx.x;
    const int l    = tid & 7;
    const int grp  = tid >> 3;
    const int row0 = blockIdx.x * 64;

    const float4* kp = reinterpret_cast<const float4*>(key + b * M);
    const float4 ka = kp[l];
    const float4 kb = kp[l + 8];
    float ks = ka.x * ka.x + ka.y * ka.y + ka.z * ka.z + ka.w * ka.w
             + kb.x * kb.x + kb.y * kb.y + kb.z * kb.z + kb.w * kb.w;

    float4 ma[2], mb[2];
#pragma unroll
    for (int u = 0; u < 2; ++u) {
        const int row = row0 + u * 32 + grp;
        const float4* mp = reinterpret_cast<const float4*>(
            mem + ((size_t)b * N + row) * M);
        ma[u] = __ldcs(mp + l);
        mb[u] = __ldcs(mp + l + 8);
    }

    float dt[2], ms[2];
#pragma unroll
    for (int u = 0; u < 2; ++u) {
        dt[u] = ka.x * ma[u].x + ka.y * ma[u].y + ka.z * ma[u].z + ka.w * ma[u].w
              + kb.x * mb[u].x + kb.y * mb[u].y + kb.z * mb[u].z + kb.w * mb[u].w;
        ms[u] = ma[u].x * ma[u].x + ma[u].y * ma[u].y + ma[u].z * ma[u].z + ma[u].w * ma[u].w
              + mb[u].x * mb[u].x + mb[u].y * mb[u].y + mb[u].z * mb[u].z + mb[u].w * mb[u].w;
    }

#pragma unroll
    for (int off = 1; off <= 4; off <<= 1) {
        ks    += __shfl_xor_sync(FULLM, ks,    off);
        dt[0] += __shfl_xor_sync(FULLM, dt[0], off);
        dt[1] += __shfl_xor_sync(FULLM, dt[1], off);
        ms[0] += __shfl_xor_sync(FULLM, ms[0], off);
        ms[1] += __shfl_xor_sync(FULLM, ms[1], off);
    }

    float esum = 0.0f;
    if (l == 0) {
        const float kn = sqrtf(ks);
        const float be = __ldg(beta + b);
#pragma unroll
        for (int u = 0; u < 2; ++u) {
            const int row = row0 + u * 32 + grp;
            const float denom = fmaxf(kn * sqrtf(ms[u]), 1e-8f);
            const float e = __expf(be * (dt[u] / denom));
            g_s[b * N + row] = e;
            esum += e;
        }
    }

    __shared__ float sred[8];
#pragma unroll
    for (int o = 16; o > 0; o >>= 1)
        esum += __shfl_xor_sync(FULLM, esum, o);
    if ((tid & 31) == 0) sred[tid >> 5] = esum;
    __syncthreads();
    if (tid == 0) {
        float s = 0.0f;
#pragma unroll
        for (int w = 0; w < 8; ++w) s += sred[w];
        g_part[b * 256 + blockIdx.x] = s;
    }
}

// ---------------------------------------------------------------------------
// k2 with PDL + shuffle halos. Preamble (overlaps k1 tail): last[] vectors,
// scalars, 2 CTA-edge last values. Post-sync: 4 vector g_s loads per thread
// (+ warp0's 8 partial loads), halos entirely from shuffles / 32-float smem
// edge table / 2 scalar CTA-edge loads. Cluster-4, 256 CTAs x 256 thr;
// renorm sum combined across the cluster via DSMEM in fixed rank order.
// ---------------------------------------------------------------------------
__global__ __launch_bounds__(256) __cluster_dims__(4, 1, 1)
void k2_address(
    const float* __restrict__ gate,     // [B,1]
    const float* __restrict__ shift,    // [B,3]
    const float* __restrict__ sharpen,  // [B,1]
    const float* __restrict__ last,     // [B,N]
    float* __restrict__ out)            // [B,N]
{
    cg::cluster_group cluster = cg::this_cluster();

    const int cta  = blockIdx.x;     // 0..255
    const int b    = cta >> 2;
    const int q    = cta & 3;        // quarter of the batch (== cluster rank)
    const int tid  = threadIdx.x;
    const int warp = tid >> 5;       // 0..7
    const int lane = tid & 31;

    __shared__ float sred[8];
    __shared__ float sS;
    __shared__ float edgeL[32];      // [warp*4+k] : lane0's  w4[k].x
    __shared__ float edgeR[32];      // [warp*4+k] : lane31's w4[k].w
    __shared__ float sCtaL, sCtaR;
    __shared__ float cpsum;          // DSMEM target

    // ======= PDL preamble: everything independent of k1's output =======
    const int base4 = (b << 12) + (q << 10);
    const float4* lp4 = reinterpret_cast<const float4*>(last);

    float4 a4[4];
#pragma unroll
    for (int k = 0; k < 4; ++k)
        a4[k] = lp4[base4 + k * 256 + tid];

    // CTA-circular edge indices + last[] values (2 threads)
    int   edgeIdx = -1;
    float edgeLast = 0.0f;
    if (tid == 0)   edgeIdx = b * N + (((q << 12) + N - 1) & (N - 1));
    if (tid == 255) edgeIdx = b * N + (((q << 12) + 4096) & (N - 1));
    if (edgeIdx >= 0) edgeLast = last[edgeIdx];

    const float g  = __ldg(gate + b);
    const float og = 1.0f - g;
    const float s0 = __ldg(shift + b * 3 + 0);
    const float s1 = __ldg(shift + b * 3 + 1);
    const float s2 = __ldg(shift + b * 3 + 2);
    const float sh = __ldg(sharpen + b);

    // ======= wait for k1 grid completion (memory-visible) =======
    cudaGridDependencySynchronize();

    // post-sync loads first (front-batched, overlap the reduction below)
    const float4* sp4 = reinterpret_cast<const float4*>(g_s);
    float4 e4[4];
#pragma unroll
    for (int k = 0; k < 4; ++k)
        e4[k] = sp4[base4 + k * 256 + tid];

    float edgeS = 0.0f;
    if (edgeIdx >= 0) edgeS = g_s[edgeIdx];

    // softmax denominator from k1 partials (warp 0)
    if (warp == 0) {
        const float* pp = g_part + b * 256;
        float S = 0.0f;
#pragma unroll
        for (int j = 0; j < 8; ++j) S += pp[j * 32 + lane];
#pragma unroll
        for (int o = 16; o > 0; o >>= 1)
            S += __shfl_xor_sync(FULLM, S, o);
        if (lane == 0) sS = S;
    }
    __syncthreads();

    const float gS = g / sS;

    // ---- gate interpolation in registers; publish edges ----
    float4 w4[4];
#pragma unroll
    for (int k = 0; k < 4; ++k) {
        w4[k].x = fmaf(gS, e4[k].x, og * a4[k].x);
        w4[k].y = fmaf(gS, e4[k].y, og * a4[k].y);
        w4[k].z = fmaf(gS, e4[k].z, og * a4[k].z);
        w4[k].w = fmaf(gS, e4[k].w, og * a4[k].w);
    }
    if (lane == 0) {
#pragma unroll
        for (int k = 0; k < 4; ++k) edgeL[warp * 4 + k] = w4[k].x;
    }
    if (lane == 31) {
#pragma unroll
        for (int k = 0; k < 4; ++k) edgeR[warp * 4 + k] = w4[k].w;
    }
    if (tid == 0)   sCtaL = fmaf(gS, edgeS, og * edgeLast);
    if (tid == 255) sCtaR = fmaf(gS, edgeS, og * edgeLast);
    __syncthreads();

    // ---- circular 3-tap conv + sharpen; halos via shuffles + edge table ----
    float4 p4[4];
    float psum = 0.0f;
#pragma unroll
    for (int k = 0; k < 4; ++k) {
        float left = __shfl_up_sync(FULLM, w4[k].w, 1);
        if (lane == 0)
            left = (warp > 0) ? edgeR[(warp - 1) * 4 + k]
                 : (k > 0)    ? edgeR[7 * 4 + (k - 1)]
                              : sCtaL;
        float right = __shfl_down_sync(FULLM, w4[k].x, 1);
        if (lane == 31)
            right = (warp < 7) ? edgeL[(warp + 1) * 4 + k]
                  : (k < 3)    ? edgeL[k + 1]
                               : sCtaR;

        p4[k].x = __powf(s0 * left    + s1 * w4[k].x + s2 * w4[k].y, sh);
        p4[k].y = __powf(s0 * w4[k].x + s1 * w4[k].y + s2 * w4[k].z, sh);
        p4[k].z = __powf(s0 * w4[k].y + s1 * w4[k].z + s2 * w4[k].w, sh);
        p4[k].w = __powf(s0 * w4[k].z + s1 * w4[k].w + s2 * right,  sh);
        psum += p4[k].x + p4[k].y + p4[k].z + p4[k].w;
    }

    // ---- CTA psum reduce (deterministic) ----
#pragma unroll
    for (int o = 16; o > 0; o >>= 1)
        psum += __shfl_xor_sync(FULLM, psum, o);
    if (lane == 0) sred[warp] = psum;
    __syncthreads();
    if (tid == 0) {
        float x = 0.0f;
#pragma unroll
        for (int w = 0; w < 8; ++w) x += sred[w];
        cpsum = x;
    }

    // ---- cluster combine via DSMEM (fixed rank order -> deterministic) ----
    cluster.sync();
    float P = 0.0f;
#pragma unroll
    for (int r = 0; r < 4; ++r)
        P += *cluster.map_shared_rank(&cpsum, r);
    cluster.sync();  // keep peer smem alive until everyone has read

    const float invP = 1.0f / (P + 1e-16f);

    float4* op4 = reinterpret_cast<float4*>(out);
#pragma unroll
    for (int k = 0; k < 4; ++k) {
        float4 p = p4[k];
        p.x *= invP; p.y *= invP; p.z *= invP; p.w *= invP;
        op4[base4 + k * 256 + tid] = p;
    }
}

extern "C" void kernel_launch(void* const* d_in, const int* in_sizes, int n_in,
                              void* d_out, int out_size) {
    const float* key     = (const float*)d_in[0];
    const float* beta    = (const float*)d_in[1];
    const float* gate    = (const float*)d_in[2];
    const float* shift   = (const float*)d_in[3];
    const float* sharpen = (const float*)d_in[4];
    const float* last    = (const float*)d_in[5];
    const float* mem     = (const float*)d_in[6];
    float* out = (float*)d_out;

    dim3 g1(N / 64, B);
    k1_logits<<<g1, 256>>>(key, beta, mem);

    // k2 with programmatic dependent launch: overlap its preamble with k1.
    cudaLaunchConfig_t cfg = {};
    cfg.gridDim  = dim3(B * 4);
    cfg.blockDim = dim3(256);
    cudaLaunchAttribute attrs[1];
    attrs[0].id = cudaLaunchAttributeProgrammaticStreamSerialization;
    attrs[0].val.programmaticStreamSerializationAllowed = 1;
    cfg.attrs = attrs;
    cfg.numAttrs = 1;
    cudaLaunchKernelEx(&cfg, k2_address, gate, shift, sharpen, last, out);
}